// round 16
// baseline (speedup 1.0000x reference)
#include <cuda_runtime.h>
#include <cuda_fp16.h>
#include <cstdint>
#include <cstddef>

#define DB 256
#define SB 512
#define NB 64

// ---------------- scratch (static device globals; no runtime allocation) ----
__device__ __half         g_xh[NB * SB * DB];    // fp16 hi part of embeddings
__device__ __half         g_xl[NB * SB * DB];    // fp16 lo (residual, ODE only)
__device__ float          g_mats[6][DB * DB];    // 0=P 1=B1 2=B2 3=T 4=A 5=M10
__device__ float          g_dv[DB];              // affine offset after 10 steps
__device__ unsigned       g_node[NB * DB];       // flip-encoded max (ODE branch)
__device__ float          g_p3[NB * 128], g_p4[NB * 128], g_p5[NB * 128];
// Disjoint per-branch conv weights (fp16): base = 0 (KW=3), 3 (KW=4), 7 (KW=5).
__device__ __half         g_wbh[12 * 128 * DB];  // conv weights [base+j][o][d]
__device__ __half         g_mTh[DB * DB];        // M10^T fp16 hi  [n][k]
__device__ __half         g_mTl[DB * DB];        // M10^T fp16 lo

__host__ __device__ __forceinline__ int wbase(int KW) {
    return (KW == 3) ? 0 : (KW == 4) ? 3 : 7;
}

// ---------------- mma / ldmatrix helpers (sm_80-level PTX only) -------------
__device__ __forceinline__ void mma_f16(float* c, const unsigned* a, const unsigned* b) {
    asm volatile(
        "mma.sync.aligned.m16n8k16.row.col.f32.f16.f16.f32 "
        "{%0,%1,%2,%3},{%4,%5,%6,%7},{%8,%9},{%0,%1,%2,%3};"
        : "+f"(c[0]), "+f"(c[1]), "+f"(c[2]), "+f"(c[3])
        : "r"(a[0]), "r"(a[1]), "r"(a[2]), "r"(a[3]), "r"(b[0]), "r"(b[1]));
}
#define LDSM4(R, addr)                                                        \
    asm volatile("ldmatrix.sync.aligned.m8n8.x4.shared.b16 {%0,%1,%2,%3}, [%4];" \
                 : "=r"((R)[0]), "=r"((R)[1]), "=r"((R)[2]), "=r"((R)[3])     \
                 : "r"(addr))
__device__ __forceinline__ uint32_t s2u(const void* p) {
    uint32_t a;
    asm("{ .reg .u64 t; cvta.to.shared.u64 t, %1; cvt.u32.u64 %0, t; }" : "=r"(a) : "l"(p));
    return a;
}

// ---------------- P = h*W^T ;  B1 = I + P/4 ---------------------------------
__global__ void k_prep(const float* __restrict__ W) {
    int i = blockIdx.x, j = threadIdx.x;
    float p = 0.1f * W[j * DB + i];
    g_mats[0][i * DB + j] = p;
    g_mats[1][i * DB + j] = ((i == j) ? 1.0f : 0.0f) + 0.25f * p;
}

// ---------------- C = scale*(A@B) (+I), one row per block -------------------
__global__ void __launch_bounds__(256) k_mm(int ci, int ai, int bi, float scale, int addI) {
    __shared__ float a_s[DB];
    float* C = g_mats[ci];
    const float* A = g_mats[ai];
    const float* __restrict__ Bm = g_mats[bi];
    int r = blockIdx.x;
    int j = threadIdx.x;
    a_s[j] = A[r * DB + j];
    __syncthreads();
    float acc = 0.f;
#pragma unroll 4
    for (int i0 = 0; i0 < DB; i0 += 16) {
        float bv[16];
#pragma unroll
        for (int u = 0; u < 16; u++) bv[u] = Bm[(i0 + u) * DB + j];
#pragma unroll
        for (int u = 0; u < 16; u++) acc = fmaf(a_s[i0 + u], bv[u], acc);
    }
    float v = scale * acc;
    if (addI && r == j) v += 1.0f;
    C[r * DB + j] = v;
}

// ---------------- c then d (affine offset), single block --------------------
__global__ void k_vec(const float* __restrict__ b_ode) {
    __shared__ float sv[DB], sc[DB];
    int j = threadIdx.x;
    const float* P = g_mats[0];
    const float* A = g_mats[4];
    float v = b_ode[j];
    float cacc = v;
    sv[j] = v;
    __syncthreads();
    const float coef[3] = {0.5f, 1.f / 6.f, 1.f / 24.f};
    for (int t = 0; t < 3; t++) {
        float nv = 0.f;
#pragma unroll 8
        for (int i = 0; i < DB; i++) nv = fmaf(sv[i], P[i * DB + j], nv);
        __syncthreads();
        sv[j] = nv;
        __syncthreads();
        cacc = fmaf(coef[t], nv, cacc);
    }
    sc[j] = 0.1f * cacc;
    sv[j] = 0.f;
    __syncthreads();
    for (int s = 0; s < 10; s++) {
        float nd = sc[j];
#pragma unroll 8
        for (int i = 0; i < DB; i++) nd = fmaf(sv[i], A[i * DB + j], nd);
        __syncthreads();
        sv[j] = nd;
        __syncthreads();
    }
    g_dv[j] = sv[j];
}

// ---------------- M10 transpose + fp16 hi/lo split: g_mT[n][k] = M10[k][n] --
__global__ void k_splitM() {
    int n = blockIdx.x, k = threadIdx.x;
    float val = g_mats[5][k * DB + n];
    __half h = __float2half_rn(val);
    __half l = __float2half_rn(val - __half2float(h));
    g_mTh[n * DB + k] = h;
    g_mTl[n * DB + k] = l;
}

// ---------------- zero pooling buffers --------------------------------------
__global__ void k_initpool() {
    int idx = blockIdx.x * 256 + threadIdx.x;
    if (idx < NB * DB) g_node[idx] = 0u;   // below every real float's encoding
    if (idx < NB * 128) {
        g_p3[idx] = 0.f;
        g_p4[idx] = 0.f;
        g_p5[idx] = 0.f;
    }
}

// ---------------- embedding gather + fp16 hi/lo split -----------------------
__global__ void k_gather(const int* __restrict__ ids, const float* __restrict__ emb) {
    int row = blockIdx.x * 4 + (threadIdx.x >> 6);
    int c = threadIdx.x & 63;
    int id = ids[row];
    float4 v = ((const float4*)(emb + (size_t)id * DB))[c];
    float vv[4] = {v.x, v.y, v.z, v.w};
    unsigned hbits[4], lbits[4];
#pragma unroll
    for (int k = 0; k < 4; k++) {
        __half h = __float2half_rn(vv[k]);
        __half l = __float2half_rn(vv[k] - __half2float(h));
        hbits[k] = __half_as_ushort(h);
        lbits[k] = __half_as_ushort(l);
    }
    size_t off = (size_t)row * DB + c * 4;
    *(uint2*)(g_xh + off) = make_uint2((hbits[1] << 16) | hbits[0], (hbits[3] << 16) | hbits[2]);
    *(uint2*)(g_xl + off) = make_uint2((lbits[1] << 16) | lbits[0], (lbits[3] << 16) | lbits[2]);
}

// -------- weight transpose + fp16: w[o][d][j] -> wb[base+j][o][d] -----------
__global__ void k_transw(const float* __restrict__ w, int KW) {
    int idx = blockIdx.x * 256 + threadIdx.x;
    int total = KW * DB * 128;
    if (idx >= total) return;
    int d = idx & 255;
    int o = (idx >> 8) & 127;
    int j = idx >> 15;
    float val = w[(o * DB + d) * KW + j];
    size_t off = ((size_t)(wbase(KW) + j) * 128 + o) * DB + d;
    g_wbh[off] = __float2half_rn(val);
}

// ---- conv branch: pure-fp16 HMMA implicit-GEMM (ldmatrix) + BN+ReLU+max ----
// Single MMA term: xh * wh. CTA tile: 64 timesteps x 128 channels.
// 8 warps as 2(M) x 4(N), warp 32x32. Smem pitch 72 fp16 (144 B).
template <int KW>
__global__ __launch_bounds__(256, 2) void k_conv(const float* __restrict__ cb,
                                                 const float* __restrict__ cg,
                                                 const float* __restrict__ cbe) {
    constexpr int LOUT = SB - KW + 1;
    float* pout = (KW == 3) ? g_p3 : (KW == 4) ? g_p4 : g_p5;
    const __half* wh = g_wbh + (size_t)wbase(KW) * 128 * DB;

    extern __shared__ char smraw[];
    __half* Ah = (__half*)smraw;     // 64 x 72
    __half* Bh = Ah + 64 * 72;       // 128 x 72

    int tid = threadIdx.x;
    int t0 = blockIdx.x * 64;
    int bb = blockIdx.y;
    int lane = tid & 31, warp = tid >> 5;
    int mw = warp >> 2, nw = warp & 3;
    int grp = lane >> 2, tg = lane & 3;

    // ldmatrix per-lane tile geometry
    int t4 = lane >> 3, rr = lane & 7;
    int rowA = (t4 & 1) * 8 + rr, colA = (t4 >> 1) * 8;
    int rowB = (t4 >> 1) * 8 + rr, colB = (t4 & 1) * 8;
    uint32_t aA = s2u(Ah) + (mw * 32 + rowA) * 144 + colA * 2;
    uint32_t aB = s2u(Bh) + (nw * 32 + rowB) * 144 + colB * 2;

    float acc[2][4][4];
#pragma unroll
    for (int mi = 0; mi < 2; mi++)
#pragma unroll
        for (int ni = 0; ni < 4; ni++)
#pragma unroll
            for (int k = 0; k < 4; k++) acc[mi][ni][k] = 0.f;

    for (int j = 0; j < KW; j++) {
        for (int d0 = 0; d0 < DB; d0 += 64) {
            __syncthreads();
            for (int it = tid; it < 512; it += 256) {
                int r = it >> 3, c8 = it & 7;
                int rw = t0 + r + j;
                if (rw > SB - 1) rw = SB - 1;  // clamped rows feed masked outputs
                size_t gi = ((size_t)(bb * SB + rw)) * DB + d0 + c8 * 8;
                *(uint4*)(Ah + r * 72 + c8 * 8) = *(const uint4*)(g_xh + gi);
            }
            for (int it = tid; it < 1024; it += 256) {
                int o = it >> 3, c8 = it & 7;
                size_t wi = ((size_t)(j * 128 + o)) * DB + d0 + c8 * 8;
                *(uint4*)(Bh + o * 72 + c8 * 8) = *(const uint4*)(wh + wi);
            }
            __syncthreads();
#pragma unroll
            for (int kk = 0; kk < 64; kk += 16) {
                unsigned ah[2][4], bh[4][2];
#pragma unroll
                for (int mi = 0; mi < 2; mi++) {
                    LDSM4(ah[mi], aA + mi * (16 * 144) + kk * 2);
                }
#pragma unroll
                for (int p = 0; p < 2; p++) {
                    unsigned t[4];
                    LDSM4(t, aB + p * (16 * 144) + kk * 2);
                    bh[2 * p][0] = t[0];
                    bh[2 * p][1] = t[1];
                    bh[2 * p + 1][0] = t[2];
                    bh[2 * p + 1][1] = t[3];
                }
#pragma unroll
                for (int mi = 0; mi < 2; mi++)
#pragma unroll
                    for (int ni = 0; ni < 4; ni++) {
                        mma_f16(acc[mi][ni], ah[mi], bh[ni]);
                    }
            }
        }
    }

    // epilogue: BN(eval) + ReLU + seq-max + global atomicMax
    const float inv = 0.99999500003749969f;  // 1/sqrt(1+1e-5)
#pragma unroll
    for (int ni = 0; ni < 4; ni++) {
        int c0 = nw * 32 + ni * 8 + 2 * tg, c1 = c0 + 1;
        float s0 = cg[c0] * inv, s1 = cg[c1] * inv;
        float h0 = fmaf(s0, cb[c0], cbe[c0]);
        float h1 = fmaf(s1, cb[c1], cbe[c1]);
        float m0 = 0.f, m1 = 0.f;  // ReLU floor doubles as -inf
#pragma unroll
        for (int mi = 0; mi < 2; mi++) {
            int tA = t0 + mw * 32 + mi * 16 + grp;
            const float* a = acc[mi][ni];
            if (tA < LOUT) {
                m0 = fmaxf(m0, fmaf(a[0], s0, h0));
                m1 = fmaxf(m1, fmaf(a[1], s1, h1));
            }
            if (tA + 8 < LOUT) {
                m0 = fmaxf(m0, fmaf(a[2], s0, h0));
                m1 = fmaxf(m1, fmaf(a[3], s1, h1));
            }
        }
#pragma unroll
        for (int off = 4; off < 32; off <<= 1) {
            m0 = fmaxf(m0, __shfl_xor_sync(0xffffffffu, m0, off));
            m1 = fmaxf(m1, __shfl_xor_sync(0xffffffffu, m1, off));
        }
        if (grp == 0) {
            atomicMax((int*)&pout[bb * 128 + c0], __float_as_int(m0));  // vals >= 0
            atomicMax((int*)&pout[bb * 128 + c1], __float_as_int(m1));
        }
    }
}

// ---- ODE GEMM via fp16x3 HMMA: z = x @ M10 (+dv) fused with seq-max --------
// CTA tile: 64 rows (seq) x 128 cols. Grid (8 rowchunk, 2 colchunk, 64 batch).
// 3 terms: xh*mh + xh*ml + xl*mh (error ~2^-22). Hidden in side stream.
__global__ __launch_bounds__(256, 2) void k_odem() {
    extern __shared__ char smraw[];
    __half* Ah = (__half*)smraw;     // 64 x 72
    __half* Al = Ah + 64 * 72;
    __half* Bh = Al + 64 * 72;       // 128 x 72
    __half* Bl = Bh + 128 * 72;

    int tid = threadIdx.x;
    int t0 = blockIdx.x * 64;
    int col0 = blockIdx.y * 128;
    int bb = blockIdx.z;
    int lane = tid & 31, warp = tid >> 5;
    int mw = warp >> 2, nw = warp & 3;
    int grp = lane >> 2, tg = lane & 3;

    int t4 = lane >> 3, rr = lane & 7;
    int rowA = (t4 & 1) * 8 + rr, colA = (t4 >> 1) * 8;
    int rowB = (t4 >> 1) * 8 + rr, colB = (t4 & 1) * 8;
    uint32_t aA = s2u(Ah) + (mw * 32 + rowA) * 144 + colA * 2;
    uint32_t aB = s2u(Bh) + (nw * 32 + rowB) * 144 + colB * 2;
    const uint32_t ALO = 64 * 144;
    const uint32_t BLO = 128 * 144;

    float acc[2][4][4];
#pragma unroll
    for (int mi = 0; mi < 2; mi++)
#pragma unroll
        for (int ni = 0; ni < 4; ni++)
#pragma unroll
            for (int k = 0; k < 4; k++) acc[mi][ni][k] = 0.f;

    for (int c = 0; c < 4; c++) {  // K = 256 in 4 chunks of 64
        __syncthreads();
        for (int it = tid; it < 512; it += 256) {
            int r = it >> 3, c8 = it & 7;
            size_t ax = ((size_t)(bb * SB + t0 + r)) * DB + c * 64 + c8 * 8;
            *(uint4*)(Ah + r * 72 + c8 * 8) = *(const uint4*)(g_xh + ax);
            *(uint4*)(Al + r * 72 + c8 * 8) = *(const uint4*)(g_xl + ax);
        }
        for (int it = tid; it < 1024; it += 256) {
            int r = it >> 3, c8 = it & 7;
            size_t bx = (size_t)(col0 + r) * DB + c * 64 + c8 * 8;
            *(uint4*)(Bh + r * 72 + c8 * 8) = *(const uint4*)(g_mTh + bx);
            *(uint4*)(Bl + r * 72 + c8 * 8) = *(const uint4*)(g_mTl + bx);
        }
        __syncthreads();
#pragma unroll
        for (int kk = 0; kk < 64; kk += 16) {
            unsigned ah[2][4], al[2][4], bh[4][2], bl[4][2];
#pragma unroll
            for (int mi = 0; mi < 2; mi++) {
                uint32_t ad = aA + mi * (16 * 144) + kk * 2;
                LDSM4(ah[mi], ad);
                LDSM4(al[mi], ad + ALO);
            }
#pragma unroll
            for (int p = 0; p < 2; p++) {
                unsigned t[4];
                uint32_t bd = aB + p * (16 * 144) + kk * 2;
                LDSM4(t, bd);
                bh[2 * p][0] = t[0];
                bh[2 * p][1] = t[1];
                bh[2 * p + 1][0] = t[2];
                bh[2 * p + 1][1] = t[3];
                LDSM4(t, bd + BLO);
                bl[2 * p][0] = t[0];
                bl[2 * p][1] = t[1];
                bl[2 * p + 1][0] = t[2];
                bl[2 * p + 1][1] = t[3];
            }
#pragma unroll
            for (int mi = 0; mi < 2; mi++)
#pragma unroll
                for (int ni = 0; ni < 4; ni++) {
                    mma_f16(acc[mi][ni], ah[mi], bh[ni]);
                    mma_f16(acc[mi][ni], ah[mi], bl[ni]);
                    mma_f16(acc[mi][ni], al[mi], bh[ni]);
                }
        }
    }

    // epilogue: +dv, signed seq-max, flip-encoded atomicMax
#pragma unroll
    for (int ni = 0; ni < 4; ni++) {
        int c0 = col0 + nw * 32 + ni * 8 + 2 * tg, c1 = c0 + 1;
        float d0 = g_dv[c0], d1 = g_dv[c1];
        float m0 = -3.4e38f, m1 = -3.4e38f;
#pragma unroll
        for (int mi = 0; mi < 2; mi++) {
            const float* a = acc[mi][ni];
            m0 = fmaxf(m0, fmaxf(a[0] + d0, a[2] + d0));
            m1 = fmaxf(m1, fmaxf(a[1] + d1, a[3] + d1));
        }
#pragma unroll
        for (int off = 4; off < 32; off <<= 1) {
            m0 = fmaxf(m0, __shfl_xor_sync(0xffffffffu, m0, off));
            m1 = fmaxf(m1, __shfl_xor_sync(0xffffffffu, m1, off));
        }
        if (grp == 0) {
            unsigned u0 = __float_as_uint(m0);
            u0 = (u0 & 0x80000000u) ? ~u0 : (u0 | 0x80000000u);
            atomicMax(&g_node[bb * DB + c0], u0);
            unsigned u1 = __float_as_uint(m1);
            u1 = (u1 & 0x80000000u) ? ~u1 : (u1 | 0x80000000u);
            atomicMax(&g_node[bb * DB + c1], u1);
        }
    }
}

// ---------------- final classifier ------------------------------------------
__global__ void k_final(const float* __restrict__ wc, const float* __restrict__ bc,
                        float* __restrict__ out) {
    __shared__ float f[640];
    int b = blockIdx.x, tid = threadIdx.x;
    for (int idx = tid; idx < 640; idx += 128) {
        float v;
        if (idx < 256) {
            unsigned u = g_node[b * DB + idx];
            unsigned bits = (u & 0x80000000u) ? (u & 0x7fffffffu) : ~u;
            v = __uint_as_float(bits);
        } else if (idx < 384) {
            v = g_p3[b * 128 + idx - 256];
        } else if (idx < 512) {
            v = g_p4[b * 128 + idx - 384];
        } else {
            v = g_p5[b * 128 + idx - 512];
        }
        f[idx] = v;
    }
    __syncthreads();
    if (tid < 10) {
        float s = bc[tid];
        const float* wr = wc + tid * 640;
#pragma unroll 8
        for (int i = 0; i < 640; i++) s = fmaf(f[i], wr[i], s);
        out[b * 10 + tid] = s;
    }
}

// ---------------- launch ----------------------------------------------------
extern "C" void kernel_launch(void* const* d_in, const int* in_sizes, int n_in,
                              void* d_out, int out_size) {
    const int* ids   = (const int*)d_in[0];
    const float* emb = (const float*)d_in[1];
    const float* W   = (const float*)d_in[2];
    const float* bo  = (const float*)d_in[3];
    const float* w3  = (const float*)d_in[4];
    const float* b3  = (const float*)d_in[5];
    const float* g3  = (const float*)d_in[6];
    const float* be3 = (const float*)d_in[7];
    const float* w4  = (const float*)d_in[8];
    const float* b4  = (const float*)d_in[9];
    const float* g4  = (const float*)d_in[10];
    const float* be4 = (const float*)d_in[11];
    const float* w5  = (const float*)d_in[12];
    const float* b5  = (const float*)d_in[13];
    const float* g5  = (const float*)d_in[14];
    const float* be5 = (const float*)d_in[15];
    const float* wc  = (const float*)d_in[16];
    const float* bc  = (const float*)d_in[17];
    float* out = (float*)d_out;

    static cudaStream_t s1 = 0, s2 = 0, s3 = 0;
    static cudaEvent_t e0 = 0, e1 = 0, e2 = 0, e3 = 0;
    static bool inited = false;
    if (!inited) {
        cudaStreamCreateWithFlags(&s1, cudaStreamNonBlocking);
        cudaStreamCreateWithFlags(&s2, cudaStreamNonBlocking);
        cudaStreamCreateWithFlags(&s3, cudaStreamNonBlocking);
        cudaEventCreateWithFlags(&e0, cudaEventDisableTiming);
        cudaEventCreateWithFlags(&e1, cudaEventDisableTiming);
        cudaEventCreateWithFlags(&e2, cudaEventDisableTiming);
        cudaEventCreateWithFlags(&e3, cudaEventDisableTiming);
        cudaFuncSetAttribute(k_odem, cudaFuncAttributeMaxDynamicSharedMemorySize, 55296);
        inited = true;
    }

    dim3 gc(8, 64);

    // prologue on capture-origin stream
    k_initpool<<<64, 256>>>();
    k_gather<<<(NB * SB) / 4, 256>>>(ids, emb);
    cudaEventRecord(e0, 0);

    // transw5 + conv5 on s0
    k_transw<<<(5 * DB * 128 + 255) / 256, 256>>>(w5, 5);
    k_transw<<<(3 * DB * 128 + 255) / 256, 256, 0, s2>>>(w3, 3);
    k_transw<<<(4 * DB * 128 + 255) / 256, 256, 0, s3>>>(w4, 4);

    k_conv<5><<<gc, 256, 27648>>>(b5, g5, be5);

    cudaStreamWaitEvent(s2, e0, 0);
    k_conv<3><<<gc, 256, 27648, s2>>>(b3, g3, be3);
    cudaEventRecord(e2, s2);
    cudaStreamWaitEvent(s3, e0, 0);
    k_conv<4><<<gc, 256, 27648, s3>>>(b4, g4, be4);
    cudaEventRecord(e3, s3);

    // s1: ODE precompute chain + HMMA ODE GEMM
    k_prep<<<256, 256, 0, s1>>>(W);
    k_mm<<<256, 256, 0, s1>>>(2, 0, 1, 1.f / 3.f, 1);  // B2 = I + P@B1/3
    k_mm<<<256, 256, 0, s1>>>(3, 0, 2, 0.5f, 1);       // T  = I + P@B2/2
    k_mm<<<256, 256, 0, s1>>>(4, 0, 3, 1.0f, 1);       // A  = I + P@T
    k_mm<<<256, 256, 0, s1>>>(1, 4, 4, 1.0f, 0);       // A2
    k_mm<<<256, 256, 0, s1>>>(2, 1, 1, 1.0f, 0);       // A4
    k_mm<<<256, 256, 0, s1>>>(3, 2, 2, 1.0f, 0);       // A8
    k_mm<<<256, 256, 0, s1>>>(5, 3, 1, 1.0f, 0);       // M10 = A8@A2
    k_vec<<<1, 256, 0, s1>>>(bo);
    k_splitM<<<256, 256, 0, s1>>>();
    cudaStreamWaitEvent(s1, e0, 0);
    {
        dim3 go(8, 2, NB);
        k_odem<<<go, 256, 55296, s1>>>();
    }
    cudaEventRecord(e1, s1);

    // join + classifier
    cudaStreamWaitEvent(0, e1, 0);
    cudaStreamWaitEvent(0, e2, 0);
    cudaStreamWaitEvent(0, e3, 0);
    k_final<<<64, 128>>>(wc, bc, out);
}

// round 17
// speedup vs baseline: 1.3298x; 1.3298x over previous
#include <cuda_runtime.h>
#include <cuda_fp16.h>
#include <cstdint>
#include <cstddef>

#define DB 256
#define SB 512
#define NB 64

// ---------------- scratch (static device globals; no runtime allocation) ----
__device__ __half         g_xh[NB * SB * DB];    // fp16 hi part of embeddings
__device__ __half         g_xl[NB * SB * DB];    // fp16 lo (residual, ODE only)
__device__ float          g_mats[6][DB * DB];    // 0=P 1=B1 2=B2 3=T 4=A 5=M10
__device__ float          g_dv[DB];              // affine offset after 10 steps
__device__ unsigned       g_node[NB * DB];       // flip-encoded max (ODE branch)
__device__ float          g_p3[NB * 128], g_p4[NB * 128], g_p5[NB * 128];
// Disjoint per-branch conv weights (fp16): base = 0 (KW=3), 3 (KW=4), 7 (KW=5).
__device__ __half         g_wbh[12 * 128 * DB];  // conv weights [base+j][o][d]
__device__ __half         g_mTh[DB * DB];        // M10^T fp16 hi  [n][k]
__device__ __half         g_mTl[DB * DB];        // M10^T fp16 lo

__host__ __device__ __forceinline__ int wbase(int KW) {
    return (KW == 3) ? 0 : (KW == 4) ? 3 : 7;
}

// ---------------- mma / ldmatrix / cp.async helpers (sm_80-level PTX) -------
__device__ __forceinline__ void mma_f16(float* c, const unsigned* a, const unsigned* b) {
    asm volatile(
        "mma.sync.aligned.m16n8k16.row.col.f32.f16.f16.f32 "
        "{%0,%1,%2,%3},{%4,%5,%6,%7},{%8,%9},{%0,%1,%2,%3};"
        : "+f"(c[0]), "+f"(c[1]), "+f"(c[2]), "+f"(c[3])
        : "r"(a[0]), "r"(a[1]), "r"(a[2]), "r"(a[3]), "r"(b[0]), "r"(b[1]));
}
#define LDSM4(R, addr)                                                        \
    asm volatile("ldmatrix.sync.aligned.m8n8.x4.shared.b16 {%0,%1,%2,%3}, [%4];" \
                 : "=r"((R)[0]), "=r"((R)[1]), "=r"((R)[2]), "=r"((R)[3])     \
                 : "r"(addr))
__device__ __forceinline__ uint32_t s2u(const void* p) {
    uint32_t a;
    asm("{ .reg .u64 t; cvta.to.shared.u64 t, %1; cvt.u32.u64 %0, t; }" : "=r"(a) : "l"(p));
    return a;
}
__device__ __forceinline__ void cp16(uint32_t smem, const void* g) {
    asm volatile("cp.async.cg.shared.global [%0], [%1], 16;" :: "r"(smem), "l"(g));
}
#define CP_COMMIT() asm volatile("cp.async.commit_group;" ::: "memory")
#define CP_WAIT(n)  asm volatile("cp.async.wait_group %0;" :: "n"(n) : "memory")

// ---------------- P = h*W^T ;  B1 = I + P/4 ---------------------------------
__global__ void k_prep(const float* __restrict__ W) {
    int i = blockIdx.x, j = threadIdx.x;
    float p = 0.1f * W[j * DB + i];
    g_mats[0][i * DB + j] = p;
    g_mats[1][i * DB + j] = ((i == j) ? 1.0f : 0.0f) + 0.25f * p;
}

// ---------------- C = scale*(A@B) (+I), one row per block -------------------
__global__ void __launch_bounds__(256) k_mm(int ci, int ai, int bi, float scale, int addI) {
    __shared__ float a_s[DB];
    float* C = g_mats[ci];
    const float* A = g_mats[ai];
    const float* __restrict__ Bm = g_mats[bi];
    int r = blockIdx.x;
    int j = threadIdx.x;
    a_s[j] = A[r * DB + j];
    __syncthreads();
    float acc = 0.f;
#pragma unroll 4
    for (int i0 = 0; i0 < DB; i0 += 16) {
        float bv[16];
#pragma unroll
        for (int u = 0; u < 16; u++) bv[u] = Bm[(i0 + u) * DB + j];
#pragma unroll
        for (int u = 0; u < 16; u++) acc = fmaf(a_s[i0 + u], bv[u], acc);
    }
    float v = scale * acc;
    if (addI && r == j) v += 1.0f;
    C[r * DB + j] = v;
}

// ---------------- c then d (affine offset), single block --------------------
__global__ void k_vec(const float* __restrict__ b_ode) {
    __shared__ float sv[DB], sc[DB];
    int j = threadIdx.x;
    const float* P = g_mats[0];
    const float* A = g_mats[4];
    float v = b_ode[j];
    float cacc = v;
    sv[j] = v;
    __syncthreads();
    const float coef[3] = {0.5f, 1.f / 6.f, 1.f / 24.f};
    for (int t = 0; t < 3; t++) {
        float nv = 0.f;
#pragma unroll 8
        for (int i = 0; i < DB; i++) nv = fmaf(sv[i], P[i * DB + j], nv);
        __syncthreads();
        sv[j] = nv;
        __syncthreads();
        cacc = fmaf(coef[t], nv, cacc);
    }
    sc[j] = 0.1f * cacc;
    sv[j] = 0.f;
    __syncthreads();
    for (int s = 0; s < 10; s++) {
        float nd = sc[j];
#pragma unroll 8
        for (int i = 0; i < DB; i++) nd = fmaf(sv[i], A[i * DB + j], nd);
        __syncthreads();
        sv[j] = nd;
        __syncthreads();
    }
    g_dv[j] = sv[j];
}

// ---------------- M10 transpose + fp16 hi/lo split: g_mT[n][k] = M10[k][n] --
__global__ void k_splitM() {
    int n = blockIdx.x, k = threadIdx.x;
    float val = g_mats[5][k * DB + n];
    __half h = __float2half_rn(val);
    __half l = __float2half_rn(val - __half2float(h));
    g_mTh[n * DB + k] = h;
    g_mTl[n * DB + k] = l;
}

// ---------------- zero pooling buffers --------------------------------------
__global__ void k_initpool() {
    int idx = blockIdx.x * 256 + threadIdx.x;
    if (idx < NB * DB) g_node[idx] = 0u;   // below every real float's encoding
    if (idx < NB * 128) {
        g_p3[idx] = 0.f;
        g_p4[idx] = 0.f;
        g_p5[idx] = 0.f;
    }
}

// ---------------- embedding gather + fp16 hi/lo split -----------------------
__global__ void k_gather(const int* __restrict__ ids, const float* __restrict__ emb) {
    int row = blockIdx.x * 4 + (threadIdx.x >> 6);
    int c = threadIdx.x & 63;
    int id = ids[row];
    float4 v = ((const float4*)(emb + (size_t)id * DB))[c];
    float vv[4] = {v.x, v.y, v.z, v.w};
    unsigned hbits[4], lbits[4];
#pragma unroll
    for (int k = 0; k < 4; k++) {
        __half h = __float2half_rn(vv[k]);
        __half l = __float2half_rn(vv[k] - __half2float(h));
        hbits[k] = __half_as_ushort(h);
        lbits[k] = __half_as_ushort(l);
    }
    size_t off = (size_t)row * DB + c * 4;
    *(uint2*)(g_xh + off) = make_uint2((hbits[1] << 16) | hbits[0], (hbits[3] << 16) | hbits[2]);
    *(uint2*)(g_xl + off) = make_uint2((lbits[1] << 16) | lbits[0], (lbits[3] << 16) | lbits[2]);
}

// -------- weight transpose + fp16: w[o][d][j] -> wb[base+j][o][d] -----------
__global__ void k_transw(const float* __restrict__ w, int KW) {
    int idx = blockIdx.x * 256 + threadIdx.x;
    int total = KW * DB * 128;
    if (idx >= total) return;
    int d = idx & 255;
    int o = (idx >> 8) & 127;
    int j = idx >> 15;
    float val = w[(o * DB + d) * KW + j];
    size_t off = ((size_t)(wbase(KW) + j) * 128 + o) * DB + d;
    g_wbh[off] = __float2half_rn(val);
}

// ---- conv branch: fp16 HMMA implicit-GEMM, cp.async double-buffered --------
// Single MMA term: xh * wh. CTA tile: 64 timesteps x 128 channels.
// 8 warps as 2(M) x 4(N), warp 32x32. Smem pitch 72 fp16 (144 B).
// Two 27648-B buffers: [A 64x72 | B 128x72] each; chunk c -> buffer c&1.
template <int KW>
__global__ __launch_bounds__(256, 2) void k_conv(const float* __restrict__ cb,
                                                 const float* __restrict__ cg,
                                                 const float* __restrict__ cbe) {
    constexpr int LOUT = SB - KW + 1;
    constexpr int NCH = KW * 4;
    constexpr int BUF = 27648;       // bytes per buffer
    constexpr int BOFF = 64 * 144;   // B region offset inside buffer (9216 B)
    float* pout = (KW == 3) ? g_p3 : (KW == 4) ? g_p4 : g_p5;
    const __half* wh = g_wbh + (size_t)wbase(KW) * 128 * DB;

    extern __shared__ char smraw[];
    uint32_t sbase = s2u(smraw);

    int tid = threadIdx.x;
    int t0 = blockIdx.x * 64;
    int bb = blockIdx.y;
    int lane = tid & 31, warp = tid >> 5;
    int mw = warp >> 2, nw = warp & 3;
    int grp = lane >> 2, tg = lane & 3;

    // ldmatrix per-lane tile geometry (offsets relative to buffer base)
    int t4 = lane >> 3, rr = lane & 7;
    int rowA = (t4 & 1) * 8 + rr, colA = (t4 >> 1) * 8;
    int rowB = (t4 >> 1) * 8 + rr, colB = (t4 & 1) * 8;
    uint32_t aA = (mw * 32 + rowA) * 144 + colA * 2;
    uint32_t aB = BOFF + (nw * 32 + rowB) * 144 + colB * 2;

    // async-stage chunk c into buffer c&1
    auto stage = [&](int c) {
        int j = c >> 2, d0 = (c & 3) * 64;
        uint32_t dst = sbase + (c & 1) * BUF;
#pragma unroll
        for (int it = tid; it < 512; it += 256) {
            int r = it >> 3, c8 = it & 7;
            int rw = t0 + r + j;
            if (rw > SB - 1) rw = SB - 1;  // clamped rows feed masked outputs
            size_t gi = ((size_t)(bb * SB + rw)) * DB + d0 + c8 * 8;
            cp16(dst + r * 144 + c8 * 16, g_xh + gi);
        }
#pragma unroll
        for (int it = tid; it < 1024; it += 256) {
            int o = it >> 3, c8 = it & 7;
            size_t wi = ((size_t)(j * 128 + o)) * DB + d0 + c8 * 8;
            cp16(dst + BOFF + o * 144 + c8 * 16, wh + wi);
        }
        CP_COMMIT();
    };

    float acc[2][4][4];
#pragma unroll
    for (int mi = 0; mi < 2; mi++)
#pragma unroll
        for (int ni = 0; ni < 4; ni++)
#pragma unroll
            for (int k = 0; k < 4; k++) acc[mi][ni][k] = 0.f;

    stage(0);
    for (int c = 0; c < NCH; c++) {
        if (c + 1 < NCH) {
            stage(c + 1);   // buffer (c+1)&1 was released by barrier at end of c-1
            CP_WAIT(1);     // chunk c's group complete
        } else {
            CP_WAIT(0);
        }
        __syncthreads();
        uint32_t base = sbase + (c & 1) * BUF;
#pragma unroll
        for (int kk = 0; kk < 64; kk += 16) {
            unsigned ah[2][4], bh[4][2];
#pragma unroll
            for (int mi = 0; mi < 2; mi++) {
                LDSM4(ah[mi], base + aA + mi * (16 * 144) + kk * 2);
            }
#pragma unroll
            for (int p = 0; p < 2; p++) {
                unsigned t[4];
                LDSM4(t, base + aB + p * (16 * 144) + kk * 2);
                bh[2 * p][0] = t[0];
                bh[2 * p][1] = t[1];
                bh[2 * p + 1][0] = t[2];
                bh[2 * p + 1][1] = t[3];
            }
#pragma unroll
            for (int mi = 0; mi < 2; mi++)
#pragma unroll
                for (int ni = 0; ni < 4; ni++) {
                    mma_f16(acc[mi][ni], ah[mi], bh[ni]);
                }
        }
        __syncthreads();  // release buffer c&1 for reuse at iteration c+1's stage(c+2)
    }

    // epilogue: BN(eval) + ReLU + seq-max + global atomicMax
    const float inv = 0.99999500003749969f;  // 1/sqrt(1+1e-5)
#pragma unroll
    for (int ni = 0; ni < 4; ni++) {
        int c0 = nw * 32 + ni * 8 + 2 * tg, c1 = c0 + 1;
        float s0 = cg[c0] * inv, s1 = cg[c1] * inv;
        float h0 = fmaf(s0, cb[c0], cbe[c0]);
        float h1 = fmaf(s1, cb[c1], cbe[c1]);
        float m0 = 0.f, m1 = 0.f;  // ReLU floor doubles as -inf
#pragma unroll
        for (int mi = 0; mi < 2; mi++) {
            int tA = t0 + mw * 32 + mi * 16 + grp;
            const float* a = acc[mi][ni];
            if (tA < LOUT) {
                m0 = fmaxf(m0, fmaf(a[0], s0, h0));
                m1 = fmaxf(m1, fmaf(a[1], s1, h1));
            }
            if (tA + 8 < LOUT) {
                m0 = fmaxf(m0, fmaf(a[2], s0, h0));
                m1 = fmaxf(m1, fmaf(a[3], s1, h1));
            }
        }
#pragma unroll
        for (int off = 4; off < 32; off <<= 1) {
            m0 = fmaxf(m0, __shfl_xor_sync(0xffffffffu, m0, off));
            m1 = fmaxf(m1, __shfl_xor_sync(0xffffffffu, m1, off));
        }
        if (grp == 0) {
            atomicMax((int*)&pout[bb * 128 + c0], __float_as_int(m0));  // vals >= 0
            atomicMax((int*)&pout[bb * 128 + c1], __float_as_int(m1));
        }
    }
}

// ---- ODE GEMM via fp16x3 HMMA: z = x @ M10 (+dv) fused with seq-max --------
// CTA tile: 64 rows (seq) x 128 cols. Grid (8 rowchunk, 2 colchunk, 64 batch).
// 3 terms: xh*mh + xh*ml + xl*mh (error ~2^-22). Hidden in side stream.
__global__ __launch_bounds__(256, 2) void k_odem() {
    extern __shared__ char smraw[];
    __half* Ah = (__half*)smraw;     // 64 x 72
    __half* Al = Ah + 64 * 72;
    __half* Bh = Al + 64 * 72;       // 128 x 72
    __half* Bl = Bh + 128 * 72;

    int tid = threadIdx.x;
    int t0 = blockIdx.x * 64;
    int col0 = blockIdx.y * 128;
    int bb = blockIdx.z;
    int lane = tid & 31, warp = tid >> 5;
    int mw = warp >> 2, nw = warp & 3;
    int grp = lane >> 2, tg = lane & 3;

    int t4 = lane >> 3, rr = lane & 7;
    int rowA = (t4 & 1) * 8 + rr, colA = (t4 >> 1) * 8;
    int rowB = (t4 >> 1) * 8 + rr, colB = (t4 & 1) * 8;
    uint32_t aA = s2u(Ah) + (mw * 32 + rowA) * 144 + colA * 2;
    uint32_t aB = s2u(Bh) + (nw * 32 + rowB) * 144 + colB * 2;
    const uint32_t ALO = 64 * 144;
    const uint32_t BLO = 128 * 144;

    float acc[2][4][4];
#pragma unroll
    for (int mi = 0; mi < 2; mi++)
#pragma unroll
        for (int ni = 0; ni < 4; ni++)
#pragma unroll
            for (int k = 0; k < 4; k++) acc[mi][ni][k] = 0.f;

    for (int c = 0; c < 4; c++) {  // K = 256 in 4 chunks of 64
        __syncthreads();
        for (int it = tid; it < 512; it += 256) {
            int r = it >> 3, c8 = it & 7;
            size_t ax = ((size_t)(bb * SB + t0 + r)) * DB + c * 64 + c8 * 8;
            *(uint4*)(Ah + r * 72 + c8 * 8) = *(const uint4*)(g_xh + ax);
            *(uint4*)(Al + r * 72 + c8 * 8) = *(const uint4*)(g_xl + ax);
        }
        for (int it = tid; it < 1024; it += 256) {
            int r = it >> 3, c8 = it & 7;
            size_t bx = (size_t)(col0 + r) * DB + c * 64 + c8 * 8;
            *(uint4*)(Bh + r * 72 + c8 * 8) = *(const uint4*)(g_mTh + bx);
            *(uint4*)(Bl + r * 72 + c8 * 8) = *(const uint4*)(g_mTl + bx);
        }
        __syncthreads();
#pragma unroll
        for (int kk = 0; kk < 64; kk += 16) {
            unsigned ah[2][4], al[2][4], bh[4][2], bl[4][2];
#pragma unroll
            for (int mi = 0; mi < 2; mi++) {
                uint32_t ad = aA + mi * (16 * 144) + kk * 2;
                LDSM4(ah[mi], ad);
                LDSM4(al[mi], ad + ALO);
            }
#pragma unroll
            for (int p = 0; p < 2; p++) {
                unsigned t[4];
                uint32_t bd = aB + p * (16 * 144) + kk * 2;
                LDSM4(t, bd);
                bh[2 * p][0] = t[0];
                bh[2 * p][1] = t[1];
                bh[2 * p + 1][0] = t[2];
                bh[2 * p + 1][1] = t[3];
                LDSM4(t, bd + BLO);
                bl[2 * p][0] = t[0];
                bl[2 * p][1] = t[1];
                bl[2 * p + 1][0] = t[2];
                bl[2 * p + 1][1] = t[3];
            }
#pragma unroll
            for (int mi = 0; mi < 2; mi++)
#pragma unroll
                for (int ni = 0; ni < 4; ni++) {
                    mma_f16(acc[mi][ni], ah[mi], bh[ni]);
                    mma_f16(acc[mi][ni], ah[mi], bl[ni]);
                    mma_f16(acc[mi][ni], al[mi], bh[ni]);
                }
        }
    }

    // epilogue: +dv, signed seq-max, flip-encoded atomicMax
#pragma unroll
    for (int ni = 0; ni < 4; ni++) {
        int c0 = col0 + nw * 32 + ni * 8 + 2 * tg, c1 = c0 + 1;
        float d0 = g_dv[c0], d1 = g_dv[c1];
        float m0 = -3.4e38f, m1 = -3.4e38f;
#pragma unroll
        for (int mi = 0; mi < 2; mi++) {
            const float* a = acc[mi][ni];
            m0 = fmaxf(m0, fmaxf(a[0] + d0, a[2] + d0));
            m1 = fmaxf(m1, fmaxf(a[1] + d1, a[3] + d1));
        }
#pragma unroll
        for (int off = 4; off < 32; off <<= 1) {
            m0 = fmaxf(m0, __shfl_xor_sync(0xffffffffu, m0, off));
            m1 = fmaxf(m1, __shfl_xor_sync(0xffffffffu, m1, off));
        }
        if (grp == 0) {
            unsigned u0 = __float_as_uint(m0);
            u0 = (u0 & 0x80000000u) ? ~u0 : (u0 | 0x80000000u);
            atomicMax(&g_node[bb * DB + c0], u0);
            unsigned u1 = __float_as_uint(m1);
            u1 = (u1 & 0x80000000u) ? ~u1 : (u1 | 0x80000000u);
            atomicMax(&g_node[bb * DB + c1], u1);
        }
    }
}

// ---------------- final classifier ------------------------------------------
__global__ void k_final(const float* __restrict__ wc, const float* __restrict__ bc,
                        float* __restrict__ out) {
    __shared__ float f[640];
    int b = blockIdx.x, tid = threadIdx.x;
    for (int idx = tid; idx < 640; idx += 128) {
        float v;
        if (idx < 256) {
            unsigned u = g_node[b * DB + idx];
            unsigned bits = (u & 0x80000000u) ? (u & 0x7fffffffu) : ~u;
            v = __uint_as_float(bits);
        } else if (idx < 384) {
            v = g_p3[b * 128 + idx - 256];
        } else if (idx < 512) {
            v = g_p4[b * 128 + idx - 384];
        } else {
            v = g_p5[b * 128 + idx - 512];
        }
        f[idx] = v;
    }
    __syncthreads();
    if (tid < 10) {
        float s = bc[tid];
        const float* wr = wc + tid * 640;
#pragma unroll 8
        for (int i = 0; i < 640; i++) s = fmaf(f[i], wr[i], s);
        out[b * 10 + tid] = s;
    }
}

// ---------------- launch ----------------------------------------------------
extern "C" void kernel_launch(void* const* d_in, const int* in_sizes, int n_in,
                              void* d_out, int out_size) {
    const int* ids   = (const int*)d_in[0];
    const float* emb = (const float*)d_in[1];
    const float* W   = (const float*)d_in[2];
    const float* bo  = (const float*)d_in[3];
    const float* w3  = (const float*)d_in[4];
    const float* b3  = (const float*)d_in[5];
    const float* g3  = (const float*)d_in[6];
    const float* be3 = (const float*)d_in[7];
    const float* w4  = (const float*)d_in[8];
    const float* b4  = (const float*)d_in[9];
    const float* g4  = (const float*)d_in[10];
    const float* be4 = (const float*)d_in[11];
    const float* w5  = (const float*)d_in[12];
    const float* b5  = (const float*)d_in[13];
    const float* g5  = (const float*)d_in[14];
    const float* be5 = (const float*)d_in[15];
    const float* wc  = (const float*)d_in[16];
    const float* bc  = (const float*)d_in[17];
    float* out = (float*)d_out;

    static cudaStream_t s1 = 0, s2 = 0, s3 = 0;
    static cudaEvent_t e0 = 0, e1 = 0, e2 = 0, e3 = 0;
    static bool inited = false;
    if (!inited) {
        cudaStreamCreateWithFlags(&s1, cudaStreamNonBlocking);
        cudaStreamCreateWithFlags(&s2, cudaStreamNonBlocking);
        cudaStreamCreateWithFlags(&s3, cudaStreamNonBlocking);
        cudaEventCreateWithFlags(&e0, cudaEventDisableTiming);
        cudaEventCreateWithFlags(&e1, cudaEventDisableTiming);
        cudaEventCreateWithFlags(&e2, cudaEventDisableTiming);
        cudaEventCreateWithFlags(&e3, cudaEventDisableTiming);
        cudaFuncSetAttribute(k_conv<3>, cudaFuncAttributeMaxDynamicSharedMemorySize, 55296);
        cudaFuncSetAttribute(k_conv<4>, cudaFuncAttributeMaxDynamicSharedMemorySize, 55296);
        cudaFuncSetAttribute(k_conv<5>, cudaFuncAttributeMaxDynamicSharedMemorySize, 55296);
        cudaFuncSetAttribute(k_odem, cudaFuncAttributeMaxDynamicSharedMemorySize, 55296);
        inited = true;
    }

    dim3 gc(8, 64);

    // prologue on capture-origin stream
    k_initpool<<<64, 256>>>();
    k_gather<<<(NB * SB) / 4, 256>>>(ids, emb);
    cudaEventRecord(e0, 0);

    // transw5 + conv5 on s0
    k_transw<<<(5 * DB * 128 + 255) / 256, 256>>>(w5, 5);
    k_transw<<<(3 * DB * 128 + 255) / 256, 256, 0, s2>>>(w3, 3);
    k_transw<<<(4 * DB * 128 + 255) / 256, 256, 0, s3>>>(w4, 4);

    k_conv<5><<<gc, 256, 55296>>>(b5, g5, be5);

    cudaStreamWaitEvent(s2, e0, 0);
    k_conv<3><<<gc, 256, 55296, s2>>>(b3, g3, be3);
    cudaEventRecord(e2, s2);
    cudaStreamWaitEvent(s3, e0, 0);
    k_conv<4><<<gc, 256, 55296, s3>>>(b4, g4, be4);
    cudaEventRecord(e3, s3);

    // s1: ODE precompute chain + HMMA ODE GEMM
    k_prep<<<256, 256, 0, s1>>>(W);
    k_mm<<<256, 256, 0, s1>>>(2, 0, 1, 1.f / 3.f, 1);  // B2 = I + P@B1/3
    k_mm<<<256, 256, 0, s1>>>(3, 0, 2, 0.5f, 1);       // T  = I + P@B2/2
    k_mm<<<256, 256, 0, s1>>>(4, 0, 3, 1.0f, 1);       // A  = I + P@T
    k_mm<<<256, 256, 0, s1>>>(1, 4, 4, 1.0f, 0);       // A2
    k_mm<<<256, 256, 0, s1>>>(2, 1, 1, 1.0f, 0);       // A4
    k_mm<<<256, 256, 0, s1>>>(3, 2, 2, 1.0f, 0);       // A8
    k_mm<<<256, 256, 0, s1>>>(5, 3, 1, 1.0f, 0);       // M10 = A8@A2
    k_vec<<<1, 256, 0, s1>>>(bo);
    k_splitM<<<256, 256, 0, s1>>>();
    cudaStreamWaitEvent(s1, e0, 0);
    {
        dim3 go(8, 2, NB);
        k_odem<<<go, 256, 55296, s1>>>();
    }
    cudaEventRecord(e1, s1);

    // join + classifier
    cudaStreamWaitEvent(0, e1, 0);
    cudaStreamWaitEvent(0, e2, 0);
    cudaStreamWaitEvent(0, e3, 0);
    k_final<<<64, 128>>>(wc, bc, out);
}